// round 10
// baseline (speedup 1.0000x reference)
#include <cuda_runtime.h>
#include <cstdint>

// Problem constants (match reference)
#define N_EVENTS   16
#define N_SAMPLES  32768
#define STEP_SIZE  256
#define BATCH      64

// out[b,j] = sum_e (j >= 256*idx[b,e]) ? x[b,e, j - 256*idx[b,e]] : 0
// Pure gather: ~67.6 MB compulsory reads + 8.4 MB writes, HBM-bound,
// measured ~7.1 TB/s (88% of spec).
//
// Persistent single-wave form: 1184 CTAs (148 SMs x 8 resident CTAs of
// 256 threads / 32 regs), each grid-striding over the 2048 logical tiles
// (32 chunks x 64 batches). Removes the wave-transition boundary of the
// 2048-CTA launch: a CTA's second tile issues its loads immediately behind
// the first tile's, keeping the memory system fed through what was the
// inter-wave drain.
#define THREADS    256
#define SAMPLES_PER_BLOCK (THREADS * 4)     // 1024 samples per tile
#define CHUNKS     (N_SAMPLES / SAMPLES_PER_BLOCK)  // 32
#define N_TILES    (CHUNKS * BATCH)         // 2048
#define GRID_CTAS  (148 * 8)                // 1184 = one full wave

__global__ __launch_bounds__(THREADS)
void render_gather_kernel(const float* __restrict__ x,
                          const int* __restrict__ indices,
                          float* __restrict__ out) {
    for (int tile = blockIdx.x; tile < N_TILES; tile += GRID_CTAS) {
        const int b     = tile >> 5;          // tile / CHUNKS
        const int chunk = tile & (CHUNKS - 1);
        const int j = (chunk * THREADS + threadIdx.x) * 4;  // output sample base

        const int* idx_b = indices + b * N_EVENTS;
        const float* xb = x + (size_t)b * N_EVENTS * N_SAMPLES;

        float4 acc = make_float4(0.f, 0.f, 0.f, 0.f);
        #pragma unroll
        for (int e = 0; e < N_EVENTS; e++) {
            const int t = __ldg(idx_b + e) * STEP_SIZE;   // uniform across warp
            const int k = j - t;
            // t multiple of 256, j multiple of 4 -> k multiple of 4 (16B aligned).
            // k < N_SAMPLES always holds since j < N_SAMPLES and t >= 0.
            if (k >= 0) {
                const float4 v = *reinterpret_cast<const float4*>(
                    xb + (size_t)e * N_SAMPLES + k);
                acc.x += v.x; acc.y += v.y; acc.z += v.z; acc.w += v.w;
            }
        }

        *reinterpret_cast<float4*>(out + (size_t)b * N_SAMPLES + j) = acc;
    }
}

extern "C" void kernel_launch(void* const* d_in, const int* in_sizes, int n_in,
                              void* d_out, int out_size) {
    const float* x = (const float*)d_in[0];          // (64, 16, 32768) f32
    const int* indices = (const int*)d_in[1];        // (64, 16) int32
    float* out = (float*)d_out;                      // (64, 1, 32768) f32

    render_gather_kernel<<<GRID_CTAS, THREADS>>>(x, indices, out);
}

// round 11
// speedup vs baseline: 1.0239x; 1.0239x over previous
#include <cuda_runtime.h>
#include <cstdint>

// Problem constants (match reference)
#define N_EVENTS   16
#define N_SAMPLES  32768
#define STEP_SIZE  256
#define BATCH      64

// out[b,j] = sum_e (j >= 256*idx[b,e]) ? x[b,e, j - 256*idx[b,e]] : 0
//
// The reference's scatter-add is inverted into a pure gather: each event's
// segment lands at a frame-aligned offset t = 256*idx, and positions j >= S
// are discarded, so every output sample is a predicated sum over the 16
// events. Race-free, atomic-free, and each covered input element is read
// exactly once: ~67.6 MB compulsory reads + 8.4 MB writes.
//
// Measured floor: 10.72 us = ~7.1 TB/s achieved (88% of 8 TB/s HBM spec).
// Ten controlled variants all landed in 10.72-11.01 us; verified neutral or
// negative: smem index broadcast, mirrored load balancing, 128t CTAs,
// __ldcs/__stcs cache hints, MLP front-batching @64 regs, persistent
// single-wave grid. This config is the floor.
//
// Layout: each thread produces 4 consecutive output samples (float4);
// 256 threads/CTA -> 1024 samples/CTA; grid (32 chunks, 64 batches).
// Per event each CTA reads ONE contiguous 4KB region -> clean coalesced
// DRAM streams. With blockIdx.x fastest, every 32 consecutive CTAs span the
// full coverage range, so resident waves are naturally load-balanced.
// Indices loaded directly per-thread (uniform within warp -> L1 broadcast,
// no smem, no barrier). regs=32, occupancy ~78%.
#define THREADS    256
#define SAMPLES_PER_BLOCK (THREADS * 4)

__global__ __launch_bounds__(THREADS)
void render_gather_kernel(const float* __restrict__ x,
                          const int* __restrict__ indices,
                          float* __restrict__ out) {
    const int b = blockIdx.y;
    const int j = (blockIdx.x * THREADS + threadIdx.x) * 4;  // output sample base

    const int* idx_b = indices + b * N_EVENTS;
    const float* xb = x + (size_t)b * N_EVENTS * N_SAMPLES;

    float4 acc = make_float4(0.f, 0.f, 0.f, 0.f);
    #pragma unroll
    for (int e = 0; e < N_EVENTS; e++) {
        const int t = __ldg(idx_b + e) * STEP_SIZE;   // uniform across warp
        const int k = j - t;
        // t multiple of 256, j multiple of 4 -> k multiple of 4 (16B aligned).
        // k < N_SAMPLES always holds since j < N_SAMPLES and t >= 0.
        if (k >= 0) {
            const float4 v = *reinterpret_cast<const float4*>(
                xb + (size_t)e * N_SAMPLES + k);
            acc.x += v.x; acc.y += v.y; acc.z += v.z; acc.w += v.w;
        }
    }

    *reinterpret_cast<float4*>(out + (size_t)b * N_SAMPLES + j) = acc;
}

extern "C" void kernel_launch(void* const* d_in, const int* in_sizes, int n_in,
                              void* d_out, int out_size) {
    const float* x = (const float*)d_in[0];          // (64, 16, 32768) f32
    const int* indices = (const int*)d_in[1];        // (64, 16) int32
    float* out = (float*)d_out;                      // (64, 1, 32768) f32

    dim3 grid(N_SAMPLES / SAMPLES_PER_BLOCK, BATCH); // (32, 64) = 2048 CTAs
    render_gather_kernel<<<grid, THREADS>>>(x, indices, out);
}